// round 10
// baseline (speedup 1.0000x reference)
#include <cuda_runtime.h>
#include <cuda_bf16.h>

#define BB 8
#define SS 1024
#define HH 8
#define EE 64
#define NBH (BB*HH)
#define NTOK (BB*SS)

typedef unsigned long long u64;
typedef unsigned int u32;

__device__ __align__(16) float g_attn[NTOK * EE];   // 2 MB scratch

// ---------------------------------------------------------------------------
// helpers
// ---------------------------------------------------------------------------
__device__ __forceinline__ u64 pk2(float lo, float hi) {
    u64 r; asm("mov.b64 %0, {%1, %2};" : "=l"(r) : "f"(lo), "f"(hi)); return r;
}
__device__ __forceinline__ u64 pfma(u64 a, u64 b, u64 c) {
    u64 d; asm("fma.rn.f32x2 %0, %1, %2, %3;" : "=l"(d) : "l"(a), "l"(b), "l"(c)); return d;
}
__device__ __forceinline__ float ex2(float x) {
    float y; asm("ex2.approx.f32 %0, %1;" : "=f"(y) : "f"(x)); return y;
}
// pack two fp32 -> bf16x2; first arg lands in HIGH half, second in LOW half
__device__ __forceinline__ u32 cvtpk(float hi, float lo) {
    u32 r; asm("cvt.rn.bf16x2.f32 %0, %1, %2;" : "=r"(r) : "f"(hi), "f"(lo)); return r;
}
// bf16x2 halves back to fp32 (bf16->f32 is a 16-bit shift)
__device__ __forceinline__ float bflo_f(u32 w) { return __uint_as_float(w << 16); }
__device__ __forceinline__ float bfhi_f(u32 w) { return __uint_as_float(w & 0xffff0000u); }
__device__ __forceinline__ float bfrnd(float v) {
    return __bfloat162float(__float2bfloat16(v));
}

// m16n8k16 row.col bf16 MMA, fp32 accum (HMMA fallback path, sm_80+ PTX)
#define MMA_BF16(d0,d1,d2,d3, a0,a1,a2,a3, b0,b1, c0,c1,c2,c3) \
  asm volatile("mma.sync.aligned.m16n8k16.row.col.f32.bf16.bf16.f32 " \
    "{%0,%1,%2,%3}, {%4,%5,%6,%7}, {%8,%9}, {%10,%11,%12,%13};" \
    : "=f"(d0),"=f"(d1),"=f"(d2),"=f"(d3) \
    : "r"(a0),"r"(a1),"r"(a2),"r"(a3), "r"(b0),"r"(b1), \
      "f"(c0),"f"(c1),"f"(c2),"f"(c3))

// ---------------------------------------------------------------------------
// Fused proj + attention. CTA = (bh, qtile of 256 queries), 512 threads.
//   skey (key-major, word idx XOR (key&4)):   [1024][8] u32
//   khiT/kloT (feature-major, stride 516):    [8][516] u32
// Softmax scale folded into A-fragments; weights hi/lo split (3 AV MMAs);
// denominator accumulated by 2 extra MMAs against a constant ones-B fragment
// (exact same W+L weights as numerator; no per-iter FADDs, no end shuffles).
// ---------------------------------------------------------------------------
#define ATTN_SMEM_BYTES 65792   // (8192 + 4128 + 4128) u32
#define ONES_BF16X2 0x3F803F80u

__global__ __launch_bounds__(512, 2) void attn_fused(const float* __restrict__ x,
                                                     const float* __restrict__ theta) {
    extern __shared__ __align__(16) u32 sm[];
    u32* skey = sm;                 // [1024*8]
    u32* khiT = sm + 8192;          // [8*516]
    u32* kloT = sm + 8192 + 4128;   // [8*516]

    int bh = blockIdx.x;
    int b = bh >> 3, h = bh & 7;
    int qt = blockIdx.y;
    int tid = threadIdx.x;

    float th[8];
#pragma unroll
    for (int i = 0; i < 8; i++) th[i] = __ldg(&theta[i]);

    // ---------------- build phase: keys 2*tid, 2*tid+1 ----------------
    const float* xb = x + (size_t)(b * SS) * 64 + h * 8;
    {
        float hi[2][8], lo[2][8];
#pragma unroll
        for (int j = 0; j < 2; j++) {
            int s = tid * 2 + j;
            const float4* xs = (const float4*)(xb + (size_t)s * 64);
            float4 v0 = xs[0], v1 = xs[1];
            float a[8] = {v0.x, v0.y, v0.z, v0.w, v1.x, v1.y, v1.z, v1.w};
            float c[8];
#pragma unroll
            for (int i = 0; i < 8; i++) c[i] = __cosf(a[i] + th[i]);
            float p[8];
            p[1] = c[0] * c[1];
#pragma unroll
            for (int w = 2; w < 8; w++) p[w] = p[w - 1] * c[w];
            float qq = c[1];
#pragma unroll
            for (int i = 2; i < 8; i++) qq *= c[i];
            p[0] = qq;
#pragma unroll
            for (int i = 0; i < 8; i++) {
                float hf = bfrnd(p[i]);
                hi[j][i] = hf;
                lo[j][i] = p[i] - hf;
            }
            uint4 HW = make_uint4(cvtpk(hi[j][1], hi[j][0]), cvtpk(hi[j][3], hi[j][2]),
                                  cvtpk(hi[j][5], hi[j][4]), cvtpk(hi[j][7], hi[j][6]));
            uint4 LW = make_uint4(cvtpk(lo[j][1], lo[j][0]), cvtpk(lo[j][3], lo[j][2]),
                                  cvtpk(lo[j][5], lo[j][4]), cvtpk(lo[j][7], lo[j][6]));
            uint4* kp = (uint4*)(skey + s * 8);
            if (s & 4) { kp[0] = LW; kp[1] = HW; }   // word index XOR 4
            else       { kp[0] = HW; kp[1] = LW; }
        }
        int pw = tid;
#pragma unroll
        for (int f = 0; f < 8; f++) {
            khiT[f * 516 + pw] = cvtpk(hi[1][f], hi[0][f]);   // low half = even key
            kloT[f * 516 + pw] = cvtpk(lo[1][f], lo[0][f]);
        }
    }
    __syncthreads();

    // ---------------- main loop: warp = 16 queries ----------------
    int lane = tid & 31, warp = tid >> 5;
    int g  = lane >> 2;        // 0..7
    int tc = lane & 3;         // 0..3
    int sw = g & 4;
    int hiOff = tc ^ sw;
    int loOff = hiOff ^ 4;

    int qbase = qt * 256 + warp * 16;
    int q0 = qbase + g;        // q0&4 == g&4
    int q1 = q0 + 8;

    // A-fragments with softmax scale folded in: s = kexp*(qhi+qlo), re-split
    const float kexp = 1.4426950408889634f * 0.35355339059327373f;
    u32 A0, A1, A2, A3;
    {
        u32 h0 = skey[q0 * 8 + hiOff], l0 = skey[q0 * 8 + loOff];
        u32 h1 = skey[q1 * 8 + hiOff], l1 = skey[q1 * 8 + loOff];
        float f0 = (bflo_f(h0) + bflo_f(l0)) * kexp;
        float f1 = (bfhi_f(h0) + bfhi_f(l0)) * kexp;
        float g0 = (bflo_f(h1) + bflo_f(l1)) * kexp;
        float g1 = (bfhi_f(h1) + bfhi_f(l1)) * kexp;
        float f0h = bfrnd(f0), f1h = bfrnd(f1);
        float g0h = bfrnd(g0), g1h = bfrnd(g1);
        A0 = cvtpk(f1h, f0h);
        A1 = cvtpk(g1h, g0h);
        A2 = cvtpk(f1 - f1h, f0 - f0h);
        A3 = cvtpk(g1 - g1h, g0 - g0h);
    }

    float o0 = 0.f, o1 = 0.f, o2 = 0.f, o3 = 0.f;
    float e0 = 0.f, e1 = 0.f, e2 = 0.f, e3 = 0.f;   // den accumulators (MMA D)

#pragma unroll 2
    for (int kb = 0; kb < SS; kb += 16) {
        int k1 = kb + g, k2 = kb + 8 + g;   // k&4 == g&4
        u32 bh1 = skey[k1 * 8 + hiOff];
        u32 bl1 = skey[k1 * 8 + loOff];
        u32 bh2 = skey[k2 * 8 + hiOff];
        u32 bl2 = skey[k2 * 8 + loOff];

        // scores (scale folded into A): exact fp32 dot via hi/lo split
        float d10, d11, d12, d13, d20, d21, d22, d23;
        MMA_BF16(d10, d11, d12, d13, A0, A1, A2, A3, bh1, bh1, 0.f, 0.f, 0.f, 0.f);
        MMA_BF16(d10, d11, d12, d13, A0, A1, A2, A3, bl1, bl1, d10, d11, d12, d13);
        MMA_BF16(d20, d21, d22, d23, A0, A1, A2, A3, bh2, bh2, 0.f, 0.f, 0.f, 0.f);
        MMA_BF16(d20, d21, d22, d23, A0, A1, A2, A3, bl2, bl2, d20, d21, d22, d23);

        // softmax weights straight off the MMA output
        float w10 = ex2(d10), w11 = ex2(d11);
        float w12 = ex2(d12), w13 = ex2(d13);
        float w20 = ex2(d20), w21 = ex2(d21);
        float w22 = ex2(d22), w23 = ex2(d23);

        u32 W0 = cvtpk(w11, w10);
        u32 W1 = cvtpk(w13, w12);
        u32 W2 = cvtpk(w21, w20);
        u32 W3 = cvtpk(w23, w22);
        u32 L0 = cvtpk(w11 - bfhi_f(W0), w10 - bflo_f(W0));
        u32 L1 = cvtpk(w13 - bfhi_f(W1), w12 - bflo_f(W1));
        u32 L2 = cvtpk(w21 - bfhi_f(W2), w20 - bflo_f(W2));
        u32 L3 = cvtpk(w23 - bfhi_f(W3), w22 - bflo_f(W3));

        int cw = kb >> 1;
        u32 Bh0 = khiT[g * 516 + cw + tc];
        u32 Bh1 = khiT[g * 516 + cw + 4 + tc];
        u32 Bl0 = kloT[g * 516 + cw + tc];
        u32 Bl1 = kloT[g * 516 + cw + 4 + tc];

        MMA_BF16(o0, o1, o2, o3, W0, W1, W2, W3, Bh0, Bh1, o0, o1, o2, o3);
        MMA_BF16(o0, o1, o2, o3, W0, W1, W2, W3, Bl0, Bl1, o0, o1, o2, o3);
        MMA_BF16(o0, o1, o2, o3, L0, L1, L2, L3, Bh0, Bh1, o0, o1, o2, o3);
        // denominator: same weights vs ones-B (d0 = full row-g sum, d2 = row g+8)
        MMA_BF16(e0, e1, e2, e3, W0, W1, W2, W3, ONES_BF16X2, ONES_BF16X2, e0, e1, e2, e3);
        MMA_BF16(e0, e1, e2, e3, L0, L1, L2, L3, ONES_BF16X2, ONES_BF16X2, e0, e1, e2, e3);
    }

    float i0 = __frcp_rn(e0), i1 = __frcp_rn(e2);

    int tok0 = b * SS + q0;
    int tok1 = tok0 + 8;
    float2* o2p = (float2*)g_attn;
    o2p[tok0 * 32 + h * 4 + tc] = make_float2(o0 * i0, o1 * i0);
    o2p[tok1 * 32 + h * 4 + tc] = make_float2(o2 * i1, o3 * i1);
}

// ---------------------------------------------------------------------------
// Kernel 3: out[token, e] = sum_k attn[token, k] * W[e, k]
// 512 CTAs x 128 thr; thread = token-pair x e-quad (8 outputs).
// Fill: 8 PARALLEL LDG.128 per thread (MLP=8) instead of 16 dependent rounds.
// Main loop: 1 LDS.128 of wt reused for 2 tokens -> W smem traffic halved.
// ---------------------------------------------------------------------------
__global__ __launch_bounds__(128) void combine_kernel(const float* __restrict__ W,
                                                      float* __restrict__ out) {
    __shared__ float wt[EE * 68];        // wt[k*68+e] = W[e*64+k], padded rows
    __shared__ float rows[16][68];       // 16 token rows, padded

    int tid = threadIdx.x;

    // W fill: 1024 float4 reads, 8 per thread, all independent
    const float4* W4 = (const float4*)W;
    float4 v[8];
#pragma unroll
    for (int j = 0; j < 8; j++) v[j] = W4[tid + j * 128];
#pragma unroll
    for (int j = 0; j < 8; j++) {
        int idx = tid + j * 128;          // e = idx>>4, k0 = (idx&15)*4
        int e = idx >> 4, k0 = (idx & 15) * 4;
        wt[(k0 + 0) * 68 + e] = v[j].x;
        wt[(k0 + 1) * 68 + e] = v[j].y;
        wt[(k0 + 2) * 68 + e] = v[j].z;
        wt[(k0 + 3) * 68 + e] = v[j].w;
    }

    // token rows: 16 tokens x 16 float4 = 256, 2 per thread
    int token0 = blockIdx.x * 16;
    const float4* ga4 = (const float4*)g_attn + token0 * 16;
#pragma unroll
    for (int j = 0; j < 2; j++) {
        int i = tid + j * 128;
        int t = i >> 4, kg = i & 15;
        float4 vv = ga4[i];
        rows[t][kg * 4 + 0] = vv.x; rows[t][kg * 4 + 1] = vv.y;
        rows[t][kg * 4 + 2] = vv.z; rows[t][kg * 4 + 3] = vv.w;
    }
    __syncthreads();

    int tp = tid >> 4;      // token pair 0..7 -> tokens 2tp, 2tp+1
    int og = tid & 15;      // e-quad: outputs og*4 .. og*4+3
    const ulonglong2* wt2 = (const ulonglong2*)wt;   // 17 units per row

    u64 a0 = 0, a1 = 0, c0 = 0, c1 = 0;
#pragma unroll
    for (int k = 0; k < EE; k++) {
        ulonglong2 bw = wt2[k * 17 + og];
        float r0 = rows[2 * tp + 0][k];
        float r1 = rows[2 * tp + 1][k];
        u64 rr0 = pk2(r0, r0);
        u64 rr1 = pk2(r1, r1);
        a0 = pfma(rr0, bw.x, a0);
        a1 = pfma(rr0, bw.y, a1);
        c0 = pfma(rr1, bw.x, c0);
        c1 = pfma(rr1, bw.y, c1);
    }
    ulonglong2* o2 = (ulonglong2*)out;
    int t0 = token0 + 2 * tp;
    ulonglong2 r0; r0.x = a0; r0.y = a1;
    ulonglong2 r1; r1.x = c0; r1.y = c1;
    o2[(t0 + 0) * 16 + og] = r0;
    o2[(t0 + 1) * 16 + og] = r1;
}

// ---------------------------------------------------------------------------
extern "C" void kernel_launch(void* const* d_in, const int* in_sizes, int n_in,
                              void* d_out, int out_size) {
    const float* x      = (const float*)d_in[0];   // [8,1024,64]
    const float* theta  = (const float*)d_in[1];   // [8]
    const float* Wc     = (const float*)d_in[2];   // [64,64]
    float* out          = (float*)d_out;           // [8,1024,64]

    cudaFuncSetAttribute(attn_fused, cudaFuncAttributeMaxDynamicSharedMemorySize,
                         ATTN_SMEM_BYTES);

    dim3 agrid(NBH, SS / 256);
    attn_fused<<<agrid, 512, ATTN_SMEM_BYTES>>>(x, theta);

    combine_kernel<<<NTOK / 16, 128>>>(Wc, out);
}